// round 1
// baseline (speedup 1.0000x reference)
#include <cuda_runtime.h>
#include <cuda_bf16.h>
#include <cstddef>

#define N_NODES 50000
#define N_EDGES 600000
#define F 128

// ---------------- scratch (static device globals; no allocation) -------------
__device__ int   g_deg[N_NODES];
__device__ int   g_start[N_NODES];
__device__ int   g_pos[N_NODES];
__device__ float g_inv[N_NODES];
__device__ int   g_elist[N_EDGES];
__device__ float g_mean[(size_t)N_NODES * F];
__device__ float g_h1[(size_t)N_NODES * F];
__device__ float g_h2[(size_t)N_NODES * F];
__device__ int   g_csum[64];
__device__ int   g_coff[64];

// ---------------- CSR build --------------------------------------------------
__global__ void zero_deg_kernel() {
    int i = blockIdx.x * blockDim.x + threadIdx.x;
    if (i < N_NODES) g_deg[i] = 0;
}

__global__ void count_deg_kernel(const int* __restrict__ dst) {
    int e = blockIdx.x * blockDim.x + threadIdx.x;
    if (e < N_EDGES) atomicAdd(&g_deg[dst[e]], 1);
}

__global__ void chunk_sum_kernel() {
    __shared__ int s[1024];
    int i = blockIdx.x * 1024 + threadIdx.x;
    int v = (i < N_NODES) ? g_deg[i] : 0;
    s[threadIdx.x] = v;
    __syncthreads();
    for (int off = 512; off > 0; off >>= 1) {
        if (threadIdx.x < off) s[threadIdx.x] += s[threadIdx.x + off];
        __syncthreads();
    }
    if (threadIdx.x == 0) g_csum[blockIdx.x] = s[0];
}

__global__ void scan_chunks_kernel(int nchunk) {
    if (threadIdx.x == 0 && blockIdx.x == 0) {
        int acc = 0;
        for (int i = 0; i < nchunk; i++) { g_coff[i] = acc; acc += g_csum[i]; }
    }
}

__global__ void scan_block_kernel() {
    __shared__ int s[1024];
    int i = blockIdx.x * 1024 + threadIdx.x;
    int v = (i < N_NODES) ? g_deg[i] : 0;
    s[threadIdx.x] = v;
    __syncthreads();
    // Hillis-Steele inclusive scan
    for (int off = 1; off < 1024; off <<= 1) {
        int t = (threadIdx.x >= off) ? s[threadIdx.x - off] : 0;
        __syncthreads();
        s[threadIdx.x] += t;
        __syncthreads();
    }
    if (i < N_NODES) {
        int excl = g_coff[blockIdx.x] + s[threadIdx.x] - v;
        g_start[i] = excl;
        g_pos[i]   = excl;
        g_inv[i]   = 1.0f / fmaxf((float)v, 1.0f);
    }
}

__global__ void fill_edges_kernel(const int* __restrict__ src,
                                  const int* __restrict__ dst) {
    int e = blockIdx.x * blockDim.x + threadIdx.x;
    if (e < N_EDGES) {
        int p = atomicAdd(&g_pos[dst[e]], 1);
        g_elist[p] = src[e];
    }
}

// ---------------- mean aggregation (gather, warp per node) -------------------
__global__ void agg_kernel(const float* __restrict__ x) {
    int w    = (blockIdx.x * blockDim.x + threadIdx.x) >> 5;
    int lane = threadIdx.x & 31;
    if (w >= N_NODES) return;
    int s0 = g_start[w];
    int d  = g_deg[w];
    float ax = 0.f, ay = 0.f, az = 0.f, aw = 0.f;
    for (int j = 0; j < d; j++) {
        int s = g_elist[s0 + j];
        float4 v = *reinterpret_cast<const float4*>(x + (size_t)s * F + lane * 4);
        ax += v.x; ay += v.y; az += v.z; aw += v.w;
    }
    float iv = g_inv[w];
    float4 o = make_float4(ax * iv, ay * iv, az * iv, aw * iv);
    *reinterpret_cast<float4*>(g_mean + (size_t)w * F + lane * 4) = o;
}

// ---------------- fused dual GEMM: out = [relu](x@Ws + mean@Wn + b) ----------
// block tile: 64 rows x 128 cols, K chunk 16; 256 threads, 4x8 micro-tile.
__global__ void __launch_bounds__(256)
sage_gemm_kernel(const float* __restrict__ x,
                 const float* __restrict__ Ws,
                 const float* __restrict__ Wn,
                 const float* __restrict__ bias,
                 float* __restrict__ out,
                 int do_relu) {
    __shared__ float xs[64][20];
    __shared__ float ms[64][20];
    __shared__ float ws[16][128];
    __shared__ float wn[16][128];

    int tid  = threadIdx.x;
    int row0 = blockIdx.x * 64;
    int c    = tid & 15;   // column group (8 cols each)
    int r    = tid >> 4;   // row group (4 rows each)

    float acc[4][8];
#pragma unroll
    for (int i = 0; i < 4; i++)
#pragma unroll
        for (int j = 0; j < 8; j++) acc[i][j] = 0.f;

    // tile-load mapping for x/mean: one float4 per thread
    int lrow = tid >> 2;          // 0..63
    int lk   = (tid & 3) * 4;     // 0,4,8,12
    int grow = row0 + lrow;
    bool rowok = (grow < N_NODES);
    const float4* xrow = (const float4*)(x + (size_t)(rowok ? grow : 0) * F);
    const float4* mrow = (const float4*)(g_mean + (size_t)(rowok ? grow : 0) * F);

    for (int kc = 0; kc < F; kc += 16) {
        float4 xv = rowok ? xrow[(kc + lk) >> 2] : make_float4(0, 0, 0, 0);
        float4 mv = rowok ? mrow[(kc + lk) >> 2] : make_float4(0, 0, 0, 0);
        *(float4*)&xs[lrow][lk] = xv;
        *(float4*)&ms[lrow][lk] = mv;

#pragma unroll
        for (int t = 0; t < 2; t++) {
            int idx = tid + t * 256;       // float4 index within 16x128 tile
            int kk  = idx >> 5;            // 0..15
            int cq  = idx & 31;            // 0..31 (x4 floats)
            *(float4*)&ws[kk][cq * 4] =
                *(const float4*)(Ws + (size_t)(kc + kk) * F + cq * 4);
            *(float4*)&wn[kk][cq * 4] =
                *(const float4*)(Wn + (size_t)(kc + kk) * F + cq * 4);
        }
        __syncthreads();

#pragma unroll
        for (int kk = 0; kk < 16; kk++) {
            float a[4], am[4];
#pragma unroll
            for (int i = 0; i < 4; i++) {
                a[i]  = xs[r * 4 + i][kk];
                am[i] = ms[r * 4 + i][kk];
            }
            float bs[8], bn[8];
            *(float4*)&bs[0] = *(float4*)&ws[kk][c * 8];
            *(float4*)&bs[4] = *(float4*)&ws[kk][c * 8 + 4];
            *(float4*)&bn[0] = *(float4*)&wn[kk][c * 8];
            *(float4*)&bn[4] = *(float4*)&wn[kk][c * 8 + 4];
#pragma unroll
            for (int i = 0; i < 4; i++)
#pragma unroll
                for (int j = 0; j < 8; j++)
                    acc[i][j] += a[i] * bs[j] + am[i] * bn[j];
        }
        __syncthreads();
    }

    float bv[8];
    *(float4*)&bv[0] = *(const float4*)(bias + c * 8);
    *(float4*)&bv[4] = *(const float4*)(bias + c * 8 + 4);

#pragma unroll
    for (int i = 0; i < 4; i++) {
        int gr = row0 + r * 4 + i;
        if (gr < N_NODES) {
            float o[8];
#pragma unroll
            for (int j = 0; j < 8; j++) {
                float v = acc[i][j] + bv[j];
                o[j] = do_relu ? fmaxf(v, 0.f) : v;
            }
            *(float4*)(out + (size_t)gr * F + c * 8)     = *(float4*)&o[0];
            *(float4*)(out + (size_t)gr * F + c * 8 + 4) = *(float4*)&o[4];
        }
    }
}

// ---------------- launch -----------------------------------------------------
extern "C" void kernel_launch(void* const* d_in, const int* in_sizes, int n_in,
                              void* d_out, int out_size) {
    const float* feat = (const float*)d_in[0];
    const int*   src  = (const int*)d_in[1];
    const int*   dst  = (const int*)d_in[2];
    const float* W1s = (const float*)d_in[3];
    const float* W1n = (const float*)d_in[4];
    const float* b1  = (const float*)d_in[5];
    const float* W2s = (const float*)d_in[6];
    const float* W2n = (const float*)d_in[7];
    const float* b2  = (const float*)d_in[8];
    const float* W3s = (const float*)d_in[9];
    const float* W3n = (const float*)d_in[10];
    const float* b3  = (const float*)d_in[11];
    float* out = (float*)d_out;

    float *h1, *h2;
    cudaGetSymbolAddress((void**)&h1, g_h1);
    cudaGetSymbolAddress((void**)&h2, g_h2);

    const int TB = 256;
    const int nch = (N_NODES + 1023) / 1024;

    // CSR build (recomputed every call; deterministic)
    zero_deg_kernel<<<(N_NODES + TB - 1) / TB, TB>>>();
    count_deg_kernel<<<(N_EDGES + TB - 1) / TB, TB>>>(dst);
    chunk_sum_kernel<<<nch, 1024>>>();
    scan_chunks_kernel<<<1, 32>>>(nch);
    scan_block_kernel<<<nch, 1024>>>();
    fill_edges_kernel<<<(N_EDGES + TB - 1) / TB, TB>>>(src, dst);

    const int aggGrid  = (N_NODES * 32 + TB - 1) / TB;
    const int gemmGrid = (N_NODES + 63) / 64;

    // layer 1
    agg_kernel<<<aggGrid, TB>>>(feat);
    sage_gemm_kernel<<<gemmGrid, 256>>>(feat, W1s, W1n, b1, h1, 1);
    // layer 2
    agg_kernel<<<aggGrid, TB>>>(h1);
    sage_gemm_kernel<<<gemmGrid, 256>>>(h1, W2s, W2n, b2, h2, 1);
    // layer 3
    agg_kernel<<<aggGrid, TB>>>(h2);
    sage_gemm_kernel<<<gemmGrid, 256>>>(h2, W3s, W3n, b3, out, 0);
}

// round 3
// speedup vs baseline: 1.7328x; 1.7328x over previous
#include <cuda_runtime.h>
#include <cuda_bf16.h>
#include <cstdint>
#include <cstddef>

#define N_NODES 50000
#define N_EDGES 600000
#define F 128

// ---------------- scratch (static device globals) ----------------------------
__device__ int   g_deg[N_NODES];
__device__ int   g_start[N_NODES];
__device__ int   g_pos[N_NODES];
__device__ float g_inv[N_NODES];
__device__ int   g_elist[N_EDGES];
__device__ int   g_csum[64];
__device__ int   g_coff[64];

__device__ __align__(16) __nv_bfloat16 g_a0hi[N_NODES * F];
__device__ __align__(16) __nv_bfloat16 g_a0lo[N_NODES * F];
__device__ __align__(16) __nv_bfloat16 g_a1hi[N_NODES * F];
__device__ __align__(16) __nv_bfloat16 g_a1lo[N_NODES * F];
__device__ __align__(16) __nv_bfloat16 g_a2hi[N_NODES * F];
__device__ __align__(16) __nv_bfloat16 g_a2lo[N_NODES * F];
__device__ __align__(16) __nv_bfloat16 g_mhi[N_NODES * F];
__device__ __align__(16) __nv_bfloat16 g_mlo[N_NODES * F];
__device__ __align__(16) __nv_bfloat16 g_wts[12 * F * F];  // per layer: Wshi,Wslo,Wnhi,Wnlo

// ---------------- helpers ----------------------------------------------------
__device__ __forceinline__ uint32_t smem_u32(const void* p) {
    uint32_t a;
    asm("{ .reg .u64 t; cvta.to.shared.u64 t, %1; cvt.u32.u64 %0, t; }" : "=r"(a) : "l"(p));
    return a;
}
__device__ __forceinline__ void cp_async16(uint32_t dst, const void* src, uint32_t pbytes) {
    asm volatile("cp.async.cg.shared.global [%0], [%1], 16, %2;"
                 :: "r"(dst), "l"(src), "r"(pbytes));
}
__device__ __forceinline__ void cp_commit() { asm volatile("cp.async.commit_group;"); }
template <int N>
__device__ __forceinline__ void cp_wait() { asm volatile("cp.async.wait_group %0;" :: "n"(N)); }

__device__ __forceinline__ void ldm_x4(uint32_t* r, uint32_t addr) {
    asm volatile("ldmatrix.sync.aligned.m8n8.x4.shared.b16 {%0,%1,%2,%3}, [%4];"
                 : "=r"(r[0]), "=r"(r[1]), "=r"(r[2]), "=r"(r[3]) : "r"(addr));
}
__device__ __forceinline__ void mma_bf16(float* d, const uint32_t* a, uint32_t b0, uint32_t b1) {
    asm volatile("mma.sync.aligned.m16n8k16.row.col.f32.bf16.bf16.f32 "
                 "{%0,%1,%2,%3}, {%4,%5,%6,%7}, {%8,%9}, {%0,%1,%2,%3};"
                 : "+f"(d[0]), "+f"(d[1]), "+f"(d[2]), "+f"(d[3])
                 : "r"(a[0]), "r"(a[1]), "r"(a[2]), "r"(a[3]), "r"(b0), "r"(b1));
}

// ---------------- CSR build --------------------------------------------------
__global__ void zero_deg_kernel() {
    int i = blockIdx.x * blockDim.x + threadIdx.x;
    if (i < N_NODES) g_deg[i] = 0;
}
__global__ void count_deg_kernel(const int* __restrict__ dst) {
    int e = blockIdx.x * blockDim.x + threadIdx.x;
    if (e < N_EDGES) atomicAdd(&g_deg[dst[e]], 1);
}
__global__ void chunk_sum_kernel() {
    __shared__ int s[1024];
    int i = blockIdx.x * 1024 + threadIdx.x;
    s[threadIdx.x] = (i < N_NODES) ? g_deg[i] : 0;
    __syncthreads();
    for (int off = 512; off > 0; off >>= 1) {
        if (threadIdx.x < off) s[threadIdx.x] += s[threadIdx.x + off];
        __syncthreads();
    }
    if (threadIdx.x == 0) g_csum[blockIdx.x] = s[0];
}
__global__ void scan_chunks_kernel(int nchunk) {
    if (threadIdx.x == 0 && blockIdx.x == 0) {
        int acc = 0;
        for (int i = 0; i < nchunk; i++) { g_coff[i] = acc; acc += g_csum[i]; }
    }
}
__global__ void scan_block_kernel() {
    __shared__ int s[1024];
    int i = blockIdx.x * 1024 + threadIdx.x;
    int v = (i < N_NODES) ? g_deg[i] : 0;
    s[threadIdx.x] = v;
    __syncthreads();
    for (int off = 1; off < 1024; off <<= 1) {
        int t = (threadIdx.x >= off) ? s[threadIdx.x - off] : 0;
        __syncthreads();
        s[threadIdx.x] += t;
        __syncthreads();
    }
    if (i < N_NODES) {
        int excl = g_coff[blockIdx.x] + s[threadIdx.x] - v;
        g_start[i] = excl;
        g_pos[i]   = excl;
        g_inv[i]   = 1.0f / fmaxf((float)v, 1.0f);
    }
}
__global__ void fill_edges_kernel(const int* __restrict__ src, const int* __restrict__ dst) {
    int e = blockIdx.x * blockDim.x + threadIdx.x;
    if (e < N_EDGES) {
        int p = atomicAdd(&g_pos[dst[e]], 1);
        g_elist[p] = src[e];
    }
}

// ---------------- fp32 -> bf16 hi/lo split -----------------------------------
__device__ __forceinline__ void split1(float v, __nv_bfloat16& h, __nv_bfloat16& l) {
    h = __float2bfloat16_rn(v);
    l = __float2bfloat16_rn(v - __bfloat162float(h));
}

__global__ void split_kernel(const float* __restrict__ x,
                             __nv_bfloat16* __restrict__ hi,
                             __nv_bfloat16* __restrict__ lo, int n4) {
    int i = blockIdx.x * blockDim.x + threadIdx.x;
    if (i >= n4) return;
    float4 v = ((const float4*)x)[i];
    __align__(8) __nv_bfloat16 h[4], l[4];
    split1(v.x, h[0], l[0]); split1(v.y, h[1], l[1]);
    split1(v.z, h[2], l[2]); split1(v.w, h[3], l[3]);
    ((uint2*)hi)[i] = *(uint2*)h;
    ((uint2*)lo)[i] = *(uint2*)l;
}

// transpose + split one 128x128 weight -> [n][k] layout (col-major B for mma)
__global__ void prep_w_kernel(const float* __restrict__ W,
                              __nv_bfloat16* __restrict__ hi,
                              __nv_bfloat16* __restrict__ lo) {
    int t = blockIdx.x * blockDim.x + threadIdx.x;
    if (t >= F * F) return;
    int n = t >> 7, k = t & 127;
    float v = W[k * F + n];
    __nv_bfloat16 h, l;
    split1(v, h, l);
    hi[t] = h; lo[t] = l;
}

// ---------------- mean aggregation (warp per node, bf16 hi/lo) ---------------
__global__ void agg_kernel(const __nv_bfloat16* __restrict__ xhi,
                           const __nv_bfloat16* __restrict__ xlo) {
    int w    = (blockIdx.x * blockDim.x + threadIdx.x) >> 5;
    int lane = threadIdx.x & 31;
    if (w >= N_NODES) return;
    int s0 = g_start[w];
    int d  = g_deg[w];
    int co = lane * 4;
    float a0 = 0.f, a1 = 0.f, a2 = 0.f, a3 = 0.f;
    for (int j = 0; j < d; j++) {
        int s = g_elist[s0 + j];
        uint2 uh = *(const uint2*)(xhi + (size_t)s * F + co);
        uint2 ul = *(const uint2*)(xlo + (size_t)s * F + co);
        float2 h0 = __bfloat1622float2(*(__nv_bfloat162*)&uh.x);
        float2 h1 = __bfloat1622float2(*(__nv_bfloat162*)&uh.y);
        float2 l0 = __bfloat1622float2(*(__nv_bfloat162*)&ul.x);
        float2 l1 = __bfloat1622float2(*(__nv_bfloat162*)&ul.y);
        a0 += h0.x + l0.x; a1 += h0.y + l0.y;
        a2 += h1.x + l1.x; a3 += h1.y + l1.y;
    }
    float iv = g_inv[w];
    __align__(8) __nv_bfloat16 h[4], l[4];
    split1(a0 * iv, h[0], l[0]); split1(a1 * iv, h[1], l[1]);
    split1(a2 * iv, h[2], l[2]); split1(a3 * iv, h[3], l[3]);
    *(uint2*)(g_mhi + (size_t)w * F + co) = *(uint2*)h;
    *(uint2*)(g_mlo + (size_t)w * F + co) = *(uint2*)l;
}

// ---------------- mma.sync fused dual-GEMM -----------------------------------
// block: 128 rows x 128 cols; 8 warps as 4(m) x 2(n); warp tile 32x64.
// K_eff = 6 segments x 128 = 768, chunked by 32 with cp.async double buffer.
__global__ void __launch_bounds__(256, 2)
sage_mma_gemm(const __nv_bfloat16* __restrict__ Ahi,
              const __nv_bfloat16* __restrict__ Alo,
              const __nv_bfloat16* __restrict__ Mhi,
              const __nv_bfloat16* __restrict__ Mlo,
              const __nv_bfloat16* __restrict__ Wb,   // Wshi,Wslo,Wnhi,Wnlo ([n][k])
              const float* __restrict__ bias,
              __nv_bfloat16* __restrict__ Ohi,
              __nv_bfloat16* __restrict__ Olo,
              float* __restrict__ Ofp,
              int do_relu, int write_fp) {
    __shared__ __align__(16) char smA[2][8192];   // 128 rows x 32 bf16
    __shared__ __align__(16) char smB[2][8192];   // 128 n    x 32 bf16
    __shared__ float s_bias[F];

    int tid = threadIdx.x, lane = tid & 31, wid = tid >> 5;
    int warp_m = wid & 3, warp_n = wid >> 2;
    int row0 = blockIdx.x * 128;

    if (tid < F) s_bias[tid] = bias[tid];

    const __nv_bfloat16* Aptr[4] = {Ahi, Alo, Mhi, Mlo};
    const int AI[6] = {0, 0, 1, 2, 2, 3};
    const int BI[6] = {0, 1, 0, 2, 3, 2};

    uint32_t aB[2] = {smem_u32(smA[0]), smem_u32(smA[1])};
    uint32_t bB[2] = {smem_u32(smB[0]), smem_u32(smB[1])};

    float acc[2][8][4];
#pragma unroll
    for (int i = 0; i < 2; i++)
#pragma unroll
        for (int j = 0; j < 8; j++)
#pragma unroll
            for (int k = 0; k < 4; k++) acc[i][j][k] = 0.f;

    auto load_chunk = [&](int c, int buf) {
        int seg = c >> 2;
        int kc  = (c & 3) * 32;
        const __nv_bfloat16* Ag = Aptr[AI[seg]];
        const __nv_bfloat16* Bg = Wb + BI[seg] * (F * F);
#pragma unroll
        for (int i = 0; i < 2; i++) {
            int idx = tid + i * 256;
            int row = idx >> 2, q = idx & 3;
            uint32_t sw = (uint32_t)(row * 64 + ((q ^ ((row >> 1) & 3)) * 16));
            int gr = row0 + row;
            int grc = (gr < N_NODES) ? gr : 0;
            uint32_t p = (gr < N_NODES) ? 16u : 0u;
            cp_async16(aB[buf] + sw, Ag + (size_t)grc * F + kc + q * 8, p);
            cp_async16(bB[buf] + sw, Bg + (size_t)row * F + kc + q * 8, 16u);
        }
        cp_commit();
    };

    auto compute = [&](int buf) {
#pragma unroll
        for (int ks = 0; ks < 32; ks += 16) {
            uint32_t af[2][4];
#pragma unroll
            for (int ms = 0; ms < 2; ms++) {
                int r = warp_m * 32 + ms * 16 + (lane & 15);
                int q = (ks >> 3) + (lane >> 4);
                ldm_x4(af[ms], aB[buf] + r * 64 + ((q ^ ((r >> 1) & 3)) * 16));
            }
            uint32_t bf[4][4];
#pragma unroll
            for (int np = 0; np < 4; np++) {
                int n = warp_n * 64 + np * 16 + (lane & 7) + ((lane >> 4) << 3);
                int q = (ks >> 3) + ((lane >> 3) & 1);
                ldm_x4(bf[np], bB[buf] + n * 64 + ((q ^ ((n >> 1) & 3)) * 16));
            }
#pragma unroll
            for (int ms = 0; ms < 2; ms++)
#pragma unroll
                for (int np = 0; np < 4; np++) {
                    mma_bf16(acc[ms][np * 2 + 0], af[ms], bf[np][0], bf[np][1]);
                    mma_bf16(acc[ms][np * 2 + 1], af[ms], bf[np][2], bf[np][3]);
                }
        }
    };

    const int NC = 24;
    load_chunk(0, 0);
    for (int c = 0; c < NC; c++) {
        if (c + 1 < NC) load_chunk(c + 1, (c + 1) & 1);
        if (c + 1 < NC) cp_wait<1>(); else cp_wait<0>();
        __syncthreads();
        compute(c & 1);
        __syncthreads();
    }

    // epilogue: bias + relu + (split-bf16 | fp32) direct writes
#pragma unroll
    for (int ms = 0; ms < 2; ms++) {
#pragma unroll
        for (int half = 0; half < 2; half++) {   // c0/c1 vs c2/c3 (row, row+8)
            int gr = row0 + warp_m * 32 + ms * 16 + (lane >> 2) + half * 8;
            if (gr >= N_NODES) continue;
#pragma unroll
            for (int np = 0; np < 8; np++) {
                int col = warp_n * 64 + np * 8 + (lane & 3) * 2;
                float v0 = acc[ms][np][half * 2 + 0] + s_bias[col];
                float v1 = acc[ms][np][half * 2 + 1] + s_bias[col + 1];
                if (do_relu) { v0 = fmaxf(v0, 0.f); v1 = fmaxf(v1, 0.f); }
                size_t gi = (size_t)gr * F + col;
                if (write_fp) {
                    *(float2*)(Ofp + gi) = make_float2(v0, v1);
                } else {
                    __nv_bfloat16 h0, l0, h1, l1;
                    split1(v0, h0, l0); split1(v1, h1, l1);
                    __nv_bfloat162 hh; hh.x = h0; hh.y = h1;
                    __nv_bfloat162 ll; ll.x = l0; ll.y = l1;
                    *(__nv_bfloat162*)(Ohi + gi) = hh;
                    *(__nv_bfloat162*)(Olo + gi) = ll;
                }
            }
        }
    }
}

// ---------------- launch -----------------------------------------------------
extern "C" void kernel_launch(void* const* d_in, const int* in_sizes, int n_in,
                              void* d_out, int out_size) {
    const float* feat = (const float*)d_in[0];
    const int*   src  = (const int*)d_in[1];
    const int*   dst  = (const int*)d_in[2];
    const float* Wsl[3] = {(const float*)d_in[3], (const float*)d_in[6], (const float*)d_in[9]};
    const float* Wnl[3] = {(const float*)d_in[4], (const float*)d_in[7], (const float*)d_in[10]};
    const float* bl[3]  = {(const float*)d_in[5], (const float*)d_in[8], (const float*)d_in[11]};
    float* out = (float*)d_out;

    __nv_bfloat16 *a0hi, *a0lo, *a1hi, *a1lo, *a2hi, *a2lo, *mhi, *mlo, *wts;
    cudaGetSymbolAddress((void**)&a0hi, g_a0hi);
    cudaGetSymbolAddress((void**)&a0lo, g_a0lo);
    cudaGetSymbolAddress((void**)&a1hi, g_a1hi);
    cudaGetSymbolAddress((void**)&a1lo, g_a1lo);
    cudaGetSymbolAddress((void**)&a2hi, g_a2hi);
    cudaGetSymbolAddress((void**)&a2lo, g_a2lo);
    cudaGetSymbolAddress((void**)&mhi,  g_mhi);
    cudaGetSymbolAddress((void**)&mlo,  g_mlo);
    cudaGetSymbolAddress((void**)&wts,  g_wts);

    const int TB = 256;
    const int nch = (N_NODES + 1023) / 1024;

    // CSR build
    zero_deg_kernel<<<(N_NODES + TB - 1) / TB, TB>>>();
    count_deg_kernel<<<(N_EDGES + TB - 1) / TB, TB>>>(dst);
    chunk_sum_kernel<<<nch, 1024>>>();
    scan_chunks_kernel<<<1, 32>>>(nch);
    scan_block_kernel<<<nch, 1024>>>();
    fill_edges_kernel<<<(N_EDGES + TB - 1) / TB, TB>>>(src, dst);

    // feature + weight splits
    int n4 = N_NODES * F / 4;
    split_kernel<<<(n4 + TB - 1) / TB, TB>>>(feat, a0hi, a0lo, n4);
    for (int l = 0; l < 3; l++) {
        prep_w_kernel<<<(F * F + TB - 1) / TB, TB>>>(Wsl[l], wts + (l * 4 + 0) * F * F,
                                                              wts + (l * 4 + 1) * F * F);
        prep_w_kernel<<<(F * F + TB - 1) / TB, TB>>>(Wnl[l], wts + (l * 4 + 2) * F * F,
                                                              wts + (l * 4 + 3) * F * F);
    }

    const int aggGrid  = (N_NODES * 32 + TB - 1) / TB;
    const int gemmGrid = (N_NODES + 127) / 128;

    // layer 1
    agg_kernel<<<aggGrid, TB>>>(a0hi, a0lo);
    sage_mma_gemm<<<gemmGrid, 256>>>(a0hi, a0lo, mhi, mlo, wts + 0 * 4 * F * F,
                                     bl[0], a1hi, a1lo, out, 1, 0);
    // layer 2
    agg_kernel<<<aggGrid, TB>>>(a1hi, a1lo);
    sage_mma_gemm<<<gemmGrid, 256>>>(a1hi, a1lo, mhi, mlo, wts + 1 * 4 * F * F,
                                     bl[1], a2hi, a2lo, out, 1, 0);
    // layer 3
    agg_kernel<<<aggGrid, TB>>>(a2hi, a2lo);
    sage_mma_gemm<<<gemmGrid, 256>>>(a2hi, a2lo, mhi, mlo, wts + 2 * 4 * F * F,
                                     bl[2], a1hi, a1lo, out, 0, 1);
}

// round 4
// speedup vs baseline: 2.0438x; 1.1795x over previous
#include <cuda_runtime.h>
#include <cuda_bf16.h>
#include <cstdint>
#include <cstddef>

#define N_NODES 50000
#define N_EDGES 600000
#define F 128

// ---------------- scratch (static device globals) ----------------------------
__device__ int   g_deg[N_NODES];
__device__ int   g_start[N_NODES];
__device__ int   g_pos[N_NODES];
__device__ float g_inv[N_NODES];
__device__ int   g_elist[N_EDGES];
__device__ int   g_total;

__device__ __align__(16) __nv_bfloat16 g_a0hi[N_NODES * F];
__device__ __align__(16) __nv_bfloat16 g_a0lo[N_NODES * F];
__device__ __align__(16) __nv_bfloat16 g_a1hi[N_NODES * F];
__device__ __align__(16) __nv_bfloat16 g_a1lo[N_NODES * F];
__device__ __align__(16) __nv_bfloat16 g_a2hi[N_NODES * F];
__device__ __align__(16) __nv_bfloat16 g_a2lo[N_NODES * F];
__device__ __align__(16) __nv_bfloat16 g_mhi[N_NODES * F];
__device__ __align__(16) __nv_bfloat16 g_mlo[N_NODES * F];
__device__ __align__(16) __nv_bfloat16 g_wts[12 * F * F];  // per layer: Wshi,Wslo,Wnhi,Wnlo

// ---------------- helpers ----------------------------------------------------
__device__ __forceinline__ uint32_t smem_u32(const void* p) {
    uint32_t a;
    asm("{ .reg .u64 t; cvta.to.shared.u64 t, %1; cvt.u32.u64 %0, t; }" : "=r"(a) : "l"(p));
    return a;
}
__device__ __forceinline__ void cp_async16(uint32_t dst, const void* src, uint32_t pbytes) {
    asm volatile("cp.async.cg.shared.global [%0], [%1], 16, %2;"
                 :: "r"(dst), "l"(src), "r"(pbytes));
}
__device__ __forceinline__ void cp_commit() { asm volatile("cp.async.commit_group;"); }
template <int N>
__device__ __forceinline__ void cp_wait() { asm volatile("cp.async.wait_group %0;" :: "n"(N)); }

__device__ __forceinline__ void ldm_x4(uint32_t* r, uint32_t addr) {
    asm volatile("ldmatrix.sync.aligned.m8n8.x4.shared.b16 {%0,%1,%2,%3}, [%4];"
                 : "=r"(r[0]), "=r"(r[1]), "=r"(r[2]), "=r"(r[3]) : "r"(addr));
}
__device__ __forceinline__ void mma_bf16(float* d, const uint32_t* a, uint32_t b0, uint32_t b1) {
    asm volatile("mma.sync.aligned.m16n8k16.row.col.f32.bf16.bf16.f32 "
                 "{%0,%1,%2,%3}, {%4,%5,%6,%7}, {%8,%9}, {%0,%1,%2,%3};"
                 : "+f"(d[0]), "+f"(d[1]), "+f"(d[2]), "+f"(d[3])
                 : "r"(a[0]), "r"(a[1]), "r"(a[2]), "r"(a[3]), "r"(b0), "r"(b1));
}

// ---------------- CSR build (scan-free) --------------------------------------
__global__ void zero_deg_kernel() {
    int i = blockIdx.x * blockDim.x + threadIdx.x;
    if (i < N_NODES) g_deg[i] = 0;
    if (i == 0) g_total = 0;
}
__global__ void count_deg_kernel(const int* __restrict__ dst) {
    int e = blockIdx.x * blockDim.x + threadIdx.x;
    if (e < N_EDGES) atomicAdd(&g_deg[dst[e]], 1);
}
// contiguous-bucket assignment; bucket order unimportant for correctness
__global__ void assign_start_kernel() {
    int i = blockIdx.x * blockDim.x + threadIdx.x;
    if (i >= N_NODES) return;
    int d = g_deg[i];
    int s = atomicAdd(&g_total, d);
    g_start[i] = s;
    g_pos[i]   = s;
    g_inv[i]   = 1.0f / fmaxf((float)d, 1.0f);
}
__global__ void fill_edges_kernel(const int* __restrict__ src, const int* __restrict__ dst) {
    int e = blockIdx.x * blockDim.x + threadIdx.x;
    if (e < N_EDGES) {
        int p = atomicAdd(&g_pos[dst[e]], 1);
        g_elist[p] = src[e];
    }
}

// ---------------- fp32 -> bf16 hi/lo split -----------------------------------
__device__ __forceinline__ void split1(float v, __nv_bfloat16& h, __nv_bfloat16& l) {
    h = __float2bfloat16_rn(v);
    l = __float2bfloat16_rn(v - __bfloat162float(h));
}

__global__ void split_kernel(const float* __restrict__ x,
                             __nv_bfloat16* __restrict__ hi,
                             __nv_bfloat16* __restrict__ lo, int n4) {
    int i = blockIdx.x * blockDim.x + threadIdx.x;
    if (i >= n4) return;
    float4 v = ((const float4*)x)[i];
    __align__(8) __nv_bfloat16 h[4], l[4];
    split1(v.x, h[0], l[0]); split1(v.y, h[1], l[1]);
    split1(v.z, h[2], l[2]); split1(v.w, h[3], l[3]);
    ((uint2*)hi)[i] = *(uint2*)h;
    ((uint2*)lo)[i] = *(uint2*)l;
}

// transpose + split all six 128x128 weights in one launch.
// weight w (layer l, self/neigh s) -> g_wts slots l*4 + s*2 {hi,lo}, [n][k] layout
__global__ void prep_w_all_kernel(const float* __restrict__ W0, const float* __restrict__ W1,
                                  const float* __restrict__ W2, const float* __restrict__ W3,
                                  const float* __restrict__ W4, const float* __restrict__ W5,
                                  __nv_bfloat16* __restrict__ wts) {
    int t = blockIdx.x * blockDim.x + threadIdx.x;
    if (t >= 6 * F * F) return;
    int w = t / (F * F), r = t % (F * F);
    int n = r >> 7, k = r & 127;
    const float* Wp[6] = {W0, W1, W2, W3, W4, W5};
    float v = Wp[w][k * F + n];
    __nv_bfloat16 h, l;
    split1(v, h, l);
    int layer = w >> 1, sn = w & 1;
    size_t base = ((size_t)layer * 4 + sn * 2) * F * F;
    wts[base + r]         = h;
    wts[base + F * F + r] = l;
}

// ---------------- mean aggregation (warp per node, bf16 hi/lo) ---------------
__global__ void agg_kernel(const __nv_bfloat16* __restrict__ xhi,
                           const __nv_bfloat16* __restrict__ xlo) {
    int w    = (blockIdx.x * blockDim.x + threadIdx.x) >> 5;
    int lane = threadIdx.x & 31;
    if (w >= N_NODES) return;
    int s0 = g_start[w];
    int d  = g_deg[w];
    int co = lane * 4;
    float a0 = 0.f, a1 = 0.f, a2 = 0.f, a3 = 0.f;
    for (int j = 0; j < d; j++) {
        int s = g_elist[s0 + j];
        uint2 uh = *(const uint2*)(xhi + (size_t)s * F + co);
        uint2 ul = *(const uint2*)(xlo + (size_t)s * F + co);
        float2 h0 = __bfloat1622float2(*(__nv_bfloat162*)&uh.x);
        float2 h1 = __bfloat1622float2(*(__nv_bfloat162*)&uh.y);
        float2 l0 = __bfloat1622float2(*(__nv_bfloat162*)&ul.x);
        float2 l1 = __bfloat1622float2(*(__nv_bfloat162*)&ul.y);
        a0 += h0.x + l0.x; a1 += h0.y + l0.y;
        a2 += h1.x + l1.x; a3 += h1.y + l1.y;
    }
    float iv = g_inv[w];
    __align__(8) __nv_bfloat16 h[4], l[4];
    split1(a0 * iv, h[0], l[0]); split1(a1 * iv, h[1], l[1]);
    split1(a2 * iv, h[2], l[2]); split1(a3 * iv, h[3], l[3]);
    *(uint2*)(g_mhi + (size_t)w * F + co) = *(uint2*)h;
    *(uint2*)(g_mlo + (size_t)w * F + co) = *(uint2*)l;
}

// ---------------- mma.sync fused dual-GEMM -----------------------------------
// block: 128 rows x 128 cols; 8 warps as 4(m) x 2(n); warp tile 32x64.
// K_eff = 6 segments x 128 = 768, chunked by 64, 3-stage cp.async pipeline.
#define STAGE_BYTES 32768      // A tile 16KB + B tile 16KB
#define NSTAGE 3
#define NCHUNK 12
__global__ void __launch_bounds__(256, 2)
sage_mma_gemm(const __nv_bfloat16* __restrict__ Ahi,
              const __nv_bfloat16* __restrict__ Alo,
              const __nv_bfloat16* __restrict__ Mhi,
              const __nv_bfloat16* __restrict__ Mlo,
              const __nv_bfloat16* __restrict__ Wb,   // Wshi,Wslo,Wnhi,Wnlo ([n][k])
              const float* __restrict__ bias,
              __nv_bfloat16* __restrict__ Ohi,
              __nv_bfloat16* __restrict__ Olo,
              float* __restrict__ Ofp,
              int do_relu, int write_fp) {
    extern __shared__ __align__(16) char sm[];
    __shared__ float s_bias[F];

    int tid = threadIdx.x, lane = tid & 31, wid = tid >> 5;
    int warp_m = wid & 3, warp_n = wid >> 2;
    int row0 = blockIdx.x * 128;

    if (tid < F) s_bias[tid] = bias[tid];

    const __nv_bfloat16* Aptr[4] = {Ahi, Alo, Mhi, Mlo};
    const int AI[6] = {0, 0, 1, 2, 2, 3};
    const int BI[6] = {0, 1, 0, 2, 3, 2};
    uint32_t smb = smem_u32(sm);

    float acc[2][8][4];
#pragma unroll
    for (int i = 0; i < 2; i++)
#pragma unroll
        for (int j = 0; j < 8; j++)
#pragma unroll
            for (int k = 0; k < 4; k++) acc[i][j][k] = 0.f;

    // chunk layout: 128 rows x 64 bf16 (128B/row), swizzle quad q ^= (row & 7)
    auto load_chunk = [&](int c, int stg) {
        int seg = c >> 1;
        int kc  = (c & 1) * 64;
        const __nv_bfloat16* Ag = Aptr[AI[seg]];
        const __nv_bfloat16* Bg = Wb + BI[seg] * (F * F);
        uint32_t aB = smb + stg * STAGE_BYTES;
        uint32_t bB = aB + 16384;
#pragma unroll
        for (int i = 0; i < 4; i++) {
            int idx = tid + i * 256;             // 1024 float4 per tile
            int row = idx >> 3, q = idx & 7;
            uint32_t sw = (uint32_t)(row * 128 + ((q ^ (row & 7)) * 16));
            int gr = row0 + row;
            int grc = (gr < N_NODES) ? gr : 0;
            uint32_t p = (gr < N_NODES) ? 16u : 0u;
            cp_async16(aB + sw, Ag + (size_t)grc * F + kc + q * 8, p);
            cp_async16(bB + sw, Bg + (size_t)row * F + kc + q * 8, 16u);
        }
        cp_commit();
    };

    auto compute = [&](int stg) {
        uint32_t aB = smb + stg * STAGE_BYTES;
        uint32_t bB = aB + 16384;
#pragma unroll
        for (int ks = 0; ks < 64; ks += 16) {
            uint32_t af[2][4];
#pragma unroll
            for (int ms = 0; ms < 2; ms++) {
                int r = warp_m * 32 + ms * 16 + (lane & 15);
                int q = (ks >> 3) + (lane >> 4);
                ldm_x4(af[ms], aB + r * 128 + ((q ^ (r & 7)) * 16));
            }
            uint32_t bf[4][4];
#pragma unroll
            for (int np = 0; np < 4; np++) {
                int n = warp_n * 64 + np * 16 + (lane & 7) + ((lane >> 4) << 3);
                int q = (ks >> 3) + ((lane >> 3) & 1);
                ldm_x4(bf[np], bB + n * 128 + ((q ^ (n & 7)) * 16));
            }
#pragma unroll
            for (int ms = 0; ms < 2; ms++)
#pragma unroll
                for (int np = 0; np < 4; np++) {
                    mma_bf16(acc[ms][np * 2 + 0], af[ms], bf[np][0], bf[np][1]);
                    mma_bf16(acc[ms][np * 2 + 1], af[ms], bf[np][2], bf[np][3]);
                }
        }
    };

    load_chunk(0, 0);
    load_chunk(1, 1);
    for (int c = 0; c < NCHUNK; c++) {
        if (c + 1 < NCHUNK) cp_wait<1>(); else cp_wait<0>();
        __syncthreads();
        if (c + 2 < NCHUNK) load_chunk(c + 2, (c + 2) % NSTAGE);
        compute(c % NSTAGE);
    }

    // epilogue: bias + relu + (split-bf16 | fp32) direct writes
#pragma unroll
    for (int ms = 0; ms < 2; ms++) {
#pragma unroll
        for (int half = 0; half < 2; half++) {
            int gr = row0 + warp_m * 32 + ms * 16 + (lane >> 2) + half * 8;
            if (gr >= N_NODES) continue;
#pragma unroll
            for (int np = 0; np < 8; np++) {
                int col = warp_n * 64 + np * 8 + (lane & 3) * 2;
                float v0 = acc[ms][np][half * 2 + 0] + s_bias[col];
                float v1 = acc[ms][np][half * 2 + 1] + s_bias[col + 1];
                if (do_relu) { v0 = fmaxf(v0, 0.f); v1 = fmaxf(v1, 0.f); }
                size_t gi = (size_t)gr * F + col;
                if (write_fp) {
                    *(float2*)(Ofp + gi) = make_float2(v0, v1);
                } else {
                    __nv_bfloat16 h0, l0, h1, l1;
                    split1(v0, h0, l0); split1(v1, h1, l1);
                    __nv_bfloat162 hh; hh.x = h0; hh.y = h1;
                    __nv_bfloat162 ll; ll.x = l0; ll.y = l1;
                    *(__nv_bfloat162*)(Ohi + gi) = hh;
                    *(__nv_bfloat162*)(Olo + gi) = ll;
                }
            }
        }
    }
}

// ---------------- launch -----------------------------------------------------
extern "C" void kernel_launch(void* const* d_in, const int* in_sizes, int n_in,
                              void* d_out, int out_size) {
    const float* feat = (const float*)d_in[0];
    const int*   src  = (const int*)d_in[1];
    const int*   dst  = (const int*)d_in[2];
    const float* Wsl[3] = {(const float*)d_in[3], (const float*)d_in[6], (const float*)d_in[9]};
    const float* Wnl[3] = {(const float*)d_in[4], (const float*)d_in[7], (const float*)d_in[10]};
    const float* bl[3]  = {(const float*)d_in[5], (const float*)d_in[8], (const float*)d_in[11]};
    float* out = (float*)d_out;

    __nv_bfloat16 *a0hi, *a0lo, *a1hi, *a1lo, *a2hi, *a2lo, *mhi, *mlo, *wts;
    cudaGetSymbolAddress((void**)&a0hi, g_a0hi);
    cudaGetSymbolAddress((void**)&a0lo, g_a0lo);
    cudaGetSymbolAddress((void**)&a1hi, g_a1hi);
    cudaGetSymbolAddress((void**)&a1lo, g_a1lo);
    cudaGetSymbolAddress((void**)&a2hi, g_a2hi);
    cudaGetSymbolAddress((void**)&a2lo, g_a2lo);
    cudaGetSymbolAddress((void**)&mhi,  g_mhi);
    cudaGetSymbolAddress((void**)&mlo,  g_mlo);
    cudaGetSymbolAddress((void**)&wts,  g_wts);

    const int DSM = NSTAGE * STAGE_BYTES;  // 96KB
    cudaFuncSetAttribute(sage_mma_gemm, cudaFuncAttributeMaxDynamicSharedMemorySize, DSM);

    const int TB = 256;

    // CSR build (scan-free)
    zero_deg_kernel<<<(N_NODES + TB - 1) / TB, TB>>>();
    count_deg_kernel<<<(N_EDGES + TB - 1) / TB, TB>>>(dst);
    assign_start_kernel<<<(N_NODES + TB - 1) / TB, TB>>>();
    fill_edges_kernel<<<(N_EDGES + TB - 1) / TB, TB>>>(src, dst);

    // feature + weight splits
    int n4 = N_NODES * F / 4;
    split_kernel<<<(n4 + TB - 1) / TB, TB>>>(feat, a0hi, a0lo, n4);
    prep_w_all_kernel<<<(6 * F * F + TB - 1) / TB, TB>>>(
        Wsl[0], Wnl[0], Wsl[1], Wnl[1], Wsl[2], Wnl[2], wts);

    const int aggGrid  = (N_NODES * 32 + TB - 1) / TB;
    const int gemmGrid = (N_NODES + 127) / 128;

    // layer 1
    agg_kernel<<<aggGrid, TB>>>(a0hi, a0lo);
    sage_mma_gemm<<<gemmGrid, 256, DSM>>>(a0hi, a0lo, mhi, mlo, wts + 0 * 4 * F * F,
                                          bl[0], a1hi, a1lo, out, 1, 0);
    // layer 2
    agg_kernel<<<aggGrid, TB>>>(a1hi, a1lo);
    sage_mma_gemm<<<gemmGrid, 256, DSM>>>(a1hi, a1lo, mhi, mlo, wts + 1 * 4 * F * F,
                                          bl[1], a2hi, a2lo, out, 1, 0);
    // layer 3
    agg_kernel<<<aggGrid, TB>>>(a2hi, a2lo);
    sage_mma_gemm<<<gemmGrid, 256, DSM>>>(a2hi, a2lo, mhi, mlo, wts + 2 * 4 * F * F,
                                          bl[2], a1hi, a1lo, out, 0, 1);
}